// round 1
// baseline (speedup 1.0000x reference)
#include <cuda_runtime.h>
#include <cuda_bf16.h>
#include <cstdint>

#define DIMZ 96
#define NQ 4656          // DIMZ*(DIMZ+1)/2
#define OUT_ROW 4753     // 1 + DIMZ + NQ

// Precomputed (i,j) pairs for the upper-triangle quad terms, packed (i<<8)|j.
// __device__ global (no allocation). Filled by an idempotent init kernel.
__device__ uint16_t g_idx[NQ];

__global__ void init_idx_kernel() {
    int q = blockIdx.x * blockDim.x + threadIdx.x;
    if (q >= NQ) return;
    // row i contributes (DIMZ - i) entries; find i by cumulative count
    int i = 0, s = 0;
    while (s + (DIMZ - i) <= q) { s += DIMZ - i; ++i; }
    int j = i + (q - s);
    g_idx[q] = (uint16_t)((i << 8) | j);
}

__global__ __launch_bounds__(256) void poly_kernel(const float* __restrict__ z,
                                                   float* __restrict__ out) {
    __shared__ float zs[DIMZ];
    const int row = blockIdx.x;
    const float* zr = z + (size_t)row * DIMZ;
    for (int t = threadIdx.x; t < DIMZ; t += blockDim.x) zs[t] = zr[t];
    __syncthreads();

    float* o = out + (size_t)row * OUT_ROW;

    // k = 0 : 1.0 ; k in [1, DIMZ] : z[k-1] ; k in [DIMZ+1, OUT_ROW) : z_i*z_j
    for (int k = threadIdx.x; k < OUT_ROW; k += blockDim.x) {
        float v;
        if (k == 0) {
            v = 1.0f;
        } else if (k <= DIMZ) {
            v = zs[k - 1];
        } else {
            // index table read: 9.3 KB, L1-resident after first block on each SM
            uint16_t p = __ldg(&g_idx[k - (DIMZ + 1)]);
            v = zs[p >> 8] * zs[p & 0xFF];
        }
        o[k] = v;
    }
}

extern "C" void kernel_launch(void* const* d_in, const int* in_sizes, int n_in,
                              void* d_out, int out_size) {
    const float* z = (const float*)d_in[0];
    float* out = (float*)d_out;
    const int B = in_sizes[0] / DIMZ;   // 32768

    // Idempotent, deterministic, graph-capturable table init (runs every call).
    init_idx_kernel<<<(NQ + 255) / 256, 256>>>();
    poly_kernel<<<B, 256>>>(z, out);
}

// round 2
// speedup vs baseline: 1.1923x; 1.1923x over previous
#include <cuda_runtime.h>
#include <cstdint>

#define DIMZ 96
#define OUT_ROW 4753          // 1 + 96 + 96*97/2
#define G 4                   // rows per CTA
#define TPB 256
#define NVEC OUT_ROW          // float4s per CTA = G*OUT_ROW/4 = 4753
#define TBL_STRIDE 4760       // padded copy stride (even -> 8B aligned rows)
#define ZSTRIDE 389           // z-copy stride in floats: 389 % 32 == 5 (odd) -> conflict-free

// 4 shifted copies of the packed (a<<8|b) pair table. Copy c holds tbl[x + c],
// so a thread whose k % 4 == c reads 4 consecutive entries at an 8B-aligned
// address (k - c is a multiple of 4). ~38 KB, L1-resident within the launch.
__device__ uint16_t g_tbl[4 * TBL_STRIDE];

__global__ void init_tbl_kernel() {
    int x = blockIdx.x * blockDim.x + threadIdx.x;
    if (x >= 4 * TBL_STRIDE) return;
    int c = x / TBL_STRIDE;
    int m = x - c * TBL_STRIDE;
    int k = m + c;
    if (k > OUT_ROW - 1) k = OUT_ROW - 1;   // pad tail with a valid entry
    uint16_t p;
    if (k == 0) {
        p = (uint16_t)((96 << 8) | 96);             // 1.0 * 1.0
    } else if (k <= DIMZ) {
        p = (uint16_t)(((k - 1) << 8) | 96);        // z[k-1] * 1.0
    } else {
        int q = k - DIMZ - 1;
        int i = 0, s = 0;
        while (s + (DIMZ - i) <= q) { s += DIMZ - i; ++i; }
        int j = i + (q - s);
        p = (uint16_t)((i << 8) | j);
    }
    g_tbl[x] = p;
}

__global__ __launch_bounds__(TPB) void poly_kernel(const float* __restrict__ z,
                                                   float* __restrict__ out) {
    // 4 copies of the 4-row z tile (97 floats per row, slot 96 = 1.0 sentinel).
    // Copy g used by lanes [8g, 8g+8): bank = C + 5g + 4u (mod 32), all distinct.
    __shared__ float zsh[4 * ZSTRIDE];

    const int tid = threadIdx.x;
    const float* zr = z + (size_t)blockIdx.x * (G * DIMZ);

    for (int t = tid; t < 4 * G * 97; t += TPB) {
        int g   = t / (G * 97);
        int rem = t - g * (G * 97);
        int r   = rem / 97;
        int j   = rem - r * 97;
        zsh[g * ZSTRIDE + r * 97 + j] = (j < DIMZ) ? zr[r * DIMZ + j] : 1.0f;
    }
    __syncthreads();

    const int g = (tid & 31) >> 3;
    float4* o4 = (float4*)(out + (size_t)blockIdx.x * (G * OUT_ROW));

    for (int v = tid; v < NVEC; v += TPB) {
        const int l = v << 2;               // flat float offset within the 4-row chunk
        const int r = l / OUT_ROW;          // 0..3  (const-divide -> mul-high)
        const int k = l - r * OUT_ROW;
        const float* zb = zsh + g * ZSTRIDE + r * 97;
        float4 res;

        if (k + 3 < OUT_ROW) {              // fast path: no row wrap (4750/4753 iters)
            const int c = k & 3;            // == (4 - r) & 3
            const uint2 w = __ldg((const uint2*)(g_tbl + c * TBL_STRIDE + (k - c)));
            const uint32_t p0 = w.x & 0xFFFFu, p1 = w.x >> 16;
            const uint32_t p2 = w.y & 0xFFFFu, p3 = w.y >> 16;
            res.x = zb[p0 >> 8] * zb[p0 & 255u];
            res.y = zb[p1 >> 8] * zb[p1 & 255u];
            res.z = zb[p2 >> 8] * zb[p2 & 255u];
            res.w = zb[p3 >> 8] * zb[p3 & 255u];
        } else {                            // row-wrap path: 3 iterations per CTA
            float vals[4];
            #pragma unroll
            for (int e = 0; e < 4; e++) {
                const int le = l + e;
                const int re = le / OUT_ROW;
                const int ke = le - re * OUT_ROW;
                const uint32_t p = g_tbl[ke];   // copy 0 = unshifted table
                const float* zbe = zsh + g * ZSTRIDE + re * 97;
                vals[e] = zbe[p >> 8] * zbe[p & 255u];
            }
            res = make_float4(vals[0], vals[1], vals[2], vals[3]);
        }
        o4[v] = res;
    }
}

extern "C" void kernel_launch(void* const* d_in, const int* in_sizes, int n_in,
                              void* d_out, int out_size) {
    const float* z = (const float*)d_in[0];
    float* out = (float*)d_out;
    const int B = in_sizes[0] / DIMZ;       // 32768, divisible by G=4

    init_tbl_kernel<<<(4 * TBL_STRIDE + 255) / 256, 256>>>();
    poly_kernel<<<B / G, TPB>>>(z, out);
}